// round 1
// baseline (speedup 1.0000x reference)
#include <cuda_runtime.h>
#include <math.h>

#define BB 64
#define CC 1024
#define TT 512
#define CB 256
#define GG 8
#define CPG (CC / GG)   // 128
#define GN_EPS 1e-5f

// Scratch (allocation-free rule: __device__ globals)
__device__ float g_h[(size_t)BB * CB * TT];       // intermediate [B, Cb, T]
__device__ float g_scale[BB * CC];                // per (b,c) norm scale
__device__ float g_shift[BB * CC];                // per (b,c) norm shift

// -------------------------------------------------------------------------
// Kernel 1: GroupNorm statistics. One block per (b, g).
// Produces fused per-channel affine: xn = x * scale + shift.
// -------------------------------------------------------------------------
__global__ void gn_stats_kernel(const float* __restrict__ x,
                                const float* __restrict__ gamma,
                                const float* __restrict__ beta) {
    int bg = blockIdx.x;                 // 0..B*G-1
    int b = bg / GG, g = bg % GG;
    const float* xp = x + ((size_t)b * CC + (size_t)g * CPG) * TT;
    const int N = CPG * TT;              // 65536

    float s = 0.f, ss = 0.f;
    for (int i = threadIdx.x; i < N; i += blockDim.x) {
        float v = xp[i];
        s += v;
        ss += v * v;
    }
    __shared__ float sh_s[256];
    __shared__ float sh_ss[256];
    sh_s[threadIdx.x] = s;
    sh_ss[threadIdx.x] = ss;
    __syncthreads();
    for (int off = 128; off > 0; off >>= 1) {
        if (threadIdx.x < off) {
            sh_s[threadIdx.x]  += sh_s[threadIdx.x + off];
            sh_ss[threadIdx.x] += sh_ss[threadIdx.x + off];
        }
        __syncthreads();
    }
    float mean = sh_s[0] / (float)N;
    float var  = sh_ss[0] / (float)N - mean * mean;
    float rstd = rsqrtf(var + GN_EPS);

    if (threadIdx.x < CPG) {
        int c = g * CPG + threadIdx.x;
        float sc = rstd * gamma[c];
        g_scale[b * CC + c] = sc;
        g_shift[b * CC + c] = beta[c] - mean * sc;
    }
}

// -------------------------------------------------------------------------
// Kernel 2/3: batched SGEMM  C[b] = A @ Bsrc[b]  (+ fused epilogue)
//   A:    [M, K] row-major (weights)
//   Bsrc: [B, K, TT] (activations; optionally normalized on load)
//   out:  [B, M, TT]
// Tile: 128x128x8, 256 threads, 8x8 per thread.
// -------------------------------------------------------------------------
template <int M, int K, bool NORM_B, bool MISH, bool RES>
__global__ __launch_bounds__(256, 2)
void gemm_fused_kernel(const float* __restrict__ A,
                       const float* __restrict__ Bsrc,
                       const float* __restrict__ bias,
                       const float* __restrict__ resid,
                       float* __restrict__ out) {
    const int BM = 128, BN = 128, BK = 8;
    int b  = blockIdx.z;
    int m0 = blockIdx.y * BM;
    int n0 = blockIdx.x * BN;
    const float* Bp = Bsrc + (size_t)b * K * TT;

    __shared__ float As[BK][BM];
    __shared__ float Bs[BK][BN];

    int tid = threadIdx.x;
    int tx = tid & 15;          // 0..15  -> 8 cols each
    int ty = tid >> 4;          // 0..15  -> 8 rows each

    const float* scale = g_scale + b * CC;
    const float* shift = g_shift + b * CC;

    float acc[8][8];
#pragma unroll
    for (int i = 0; i < 8; i++)
#pragma unroll
        for (int j = 0; j < 8; j++) acc[i][j] = 0.f;

    // A-tile load indices (128x8, 4 consecutive k per thread)
    int a_idx = tid * 4;
    int a_row = a_idx / BK;
    int a_col = a_idx % BK;
    // B-tile load indices (8x128, 4 consecutive n per thread)
    int b_idx = tid * 4;
    int b_krow = b_idx / BN;
    int b_col  = b_idx % BN;

    for (int k0 = 0; k0 < K; k0 += BK) {
        // Load A tile, stored transposed As[k][m]
        {
            float4 v = *(const float4*)(A + (size_t)(m0 + a_row) * K + k0 + a_col);
            As[a_col + 0][a_row] = v.x;
            As[a_col + 1][a_row] = v.y;
            As[a_col + 2][a_row] = v.z;
            As[a_col + 3][a_row] = v.w;
        }
        // Load B tile (apply fused groupnorm if requested)
        {
            int kg = k0 + b_krow;
            float4 v = *(const float4*)(Bp + (size_t)kg * TT + n0 + b_col);
            if (NORM_B) {
                float sc = scale[kg], sh = shift[kg];
                v.x = fmaf(v.x, sc, sh);
                v.y = fmaf(v.y, sc, sh);
                v.z = fmaf(v.z, sc, sh);
                v.w = fmaf(v.w, sc, sh);
            }
            *(float4*)&Bs[b_krow][b_col] = v;
        }
        __syncthreads();

#pragma unroll
        for (int kk = 0; kk < BK; kk++) {
            float ra[8], rb[8];
#pragma unroll
            for (int i = 0; i < 8; i++) ra[i] = As[kk][ty * 8 + i];
#pragma unroll
            for (int j = 0; j < 8; j++) rb[j] = Bs[kk][tx * 8 + j];
#pragma unroll
            for (int i = 0; i < 8; i++)
#pragma unroll
                for (int j = 0; j < 8; j++)
                    acc[i][j] = fmaf(ra[i], rb[j], acc[i][j]);
        }
        __syncthreads();
    }

    // Epilogue
#pragma unroll
    for (int i = 0; i < 8; i++) {
        int m = m0 + ty * 8 + i;
        float bv = bias[m];
        float* op = out + ((size_t)b * M + m) * TT + n0 + tx * 8;
        const float* rp = RES ? (resid + ((size_t)b * M + m) * TT + n0 + tx * 8)
                              : nullptr;
        float vals[8];
#pragma unroll
        for (int j = 0; j < 8; j++) {
            float v = acc[i][j] + bv;
            if (MISH) {
                // mish(v) = v * tanh(softplus(v)); stable softplus
                float sp = (v > 20.f) ? v : log1pf(expf(v));
                v = v * tanhf(sp);
            }
            if (RES) v += rp[j];
            vals[j] = v;
        }
        *(float4*)(op + 0) = make_float4(vals[0], vals[1], vals[2], vals[3]);
        *(float4*)(op + 4) = make_float4(vals[4], vals[5], vals[6], vals[7]);
    }
}

// -------------------------------------------------------------------------
// Launch
// -------------------------------------------------------------------------
extern "C" void kernel_launch(void* const* d_in, const int* in_sizes, int n_in,
                              void* d_out, int out_size) {
    const float* x      = (const float*)d_in[0];
    const float* gamma  = (const float*)d_in[1];
    const float* beta   = (const float*)d_in[2];
    const float* w_down = (const float*)d_in[3];
    const float* b_down = (const float*)d_in[4];
    const float* w_up   = (const float*)d_in[5];
    const float* b_up   = (const float*)d_in[6];
    float* out = (float*)d_out;

    float* h_ptr = nullptr;
    cudaGetSymbolAddress((void**)&h_ptr, g_h);

    // 1) GroupNorm stats -> per-(b,c) scale/shift
    gn_stats_kernel<<<BB * GG, 256>>>(x, gamma, beta);

    // 2) down GEMM + norm-on-load + mish:  h = mish(w_down @ xn + b_down)
    //    M=256, K=1024 -> grid (T/128, M/128, B) = (4, 2, 64)
    gemm_fused_kernel<CB, CC, true, true, false>
        <<<dim3(TT / 128, CB / 128, BB), 256>>>(w_down, x, b_down, nullptr, h_ptr);

    // 3) up GEMM + bias + residual:  out = w_up @ h + b_up + x
    //    M=1024, K=256 -> grid (4, 8, 64)
    gemm_fused_kernel<CC, CB, false, false, true>
        <<<dim3(TT / 128, CC / 128, BB), 256>>>(w_up, h_ptr, b_up, x, out);
}

// round 2
// speedup vs baseline: 2.7753x; 2.7753x over previous
#include <cuda_runtime.h>
#include <math.h>
#include <stdint.h>

#define BB 64
#define CC 1024
#define TT 512
#define CBOT 256
#define GG 8
#define CPG 128
#define GN_EPS 1e-5f

#define BM 128
#define BN 128
#define BK 16
#define ASTR 20    // As row stride (floats): bank = (20m+k)%32 conflict-free
#define BSTR 132   // Bs row stride (floats): bank = (4k+n)%32 conflict-free

// Scratch (__device__ globals: allocation-free rule)
__device__ float g_h[(size_t)BB * CBOT * TT];   // mid activations, tf32-rounded
__device__ float g_scale[BB * CC];
__device__ float g_shift[BB * CC];
__device__ float g_wd[CBOT * CC];               // tf32-rounded w_down
__device__ float g_wu[CC * CBOT];               // tf32-rounded w_up

__device__ __forceinline__ uint32_t f2tf32(float f) {
    uint32_t r;
    asm("cvt.rna.tf32.f32 %0, %1;" : "=r"(r) : "f"(f));
    return r;
}
__device__ __forceinline__ void cp_async16(void* s, const void* g) {
    uint32_t sa = (uint32_t)__cvta_generic_to_shared(s);
    asm volatile("cp.async.cg.shared.global [%0], [%1], 16;" :: "r"(sa), "l"(g));
}
#define CP_COMMIT() asm volatile("cp.async.commit_group;")
#define CP_WAIT_ALL() asm volatile("cp.async.wait_group 0;")

__device__ __forceinline__ void mma_tf32(float* c, const uint32_t* a, const uint32_t* b) {
    asm volatile(
        "mma.sync.aligned.m16n8k8.row.col.f32.tf32.tf32.f32 "
        "{%0,%1,%2,%3}, {%4,%5,%6,%7}, {%8,%9}, {%0,%1,%2,%3};"
        : "+f"(c[0]), "+f"(c[1]), "+f"(c[2]), "+f"(c[3])
        : "r"(a[0]), "r"(a[1]), "r"(a[2]), "r"(a[3]), "r"(b[0]), "r"(b[1]));
}

__device__ __forceinline__ float mishf(float v) {
    float sp = (v > 20.f) ? v : log1pf(__expf(v));
    return v * tanhf(sp);
}

// -------------------------------------------------------------------------
// GroupNorm stats: one block per (b,g), 512 threads, float4 loads.
// -------------------------------------------------------------------------
__global__ void gn_stats_kernel(const float* __restrict__ x,
                                const float* __restrict__ gamma,
                                const float* __restrict__ beta) {
    int b = blockIdx.x >> 3, g = blockIdx.x & 7;
    const float4* xp = (const float4*)(x + ((size_t)b * CC + (size_t)g * CPG) * TT);
    const int N4 = CPG * TT / 4;  // 16384
    float s = 0.f, ss = 0.f;
    for (int i = threadIdx.x; i < N4; i += 512) {
        float4 v = xp[i];
        s  += v.x + v.y + v.z + v.w;
        ss += v.x*v.x + v.y*v.y + v.z*v.z + v.w*v.w;
    }
#pragma unroll
    for (int o = 16; o; o >>= 1) {
        s  += __shfl_xor_sync(0xffffffffu, s, o);
        ss += __shfl_xor_sync(0xffffffffu, ss, o);
    }
    __shared__ float ws[16], wss[16];
    int w = threadIdx.x >> 5, l = threadIdx.x & 31;
    if (l == 0) { ws[w] = s; wss[w] = ss; }
    __syncthreads();
    if (threadIdx.x < CPG) {
        float S = 0.f, SS = 0.f;
#pragma unroll
        for (int i = 0; i < 16; i++) { S += ws[i]; SS += wss[i]; }
        float mean = S / 65536.f;
        float var  = SS / 65536.f - mean * mean;
        float rstd = rsqrtf(var + GN_EPS);
        int c = g * CPG + threadIdx.x;
        float sc = rstd * gamma[c];
        g_scale[b * CC + c] = sc;
        g_shift[b * CC + c] = beta[c] - mean * sc;
    }
}

// -------------------------------------------------------------------------
// Pre-round weights to tf32 (RNA) so GEMMs can cp.async them raw.
// -------------------------------------------------------------------------
__global__ void round_w_kernel(const float* __restrict__ wd,
                               const float* __restrict__ wu) {
    int i = blockIdx.x * 256 + threadIdx.x;
    g_wd[i] = __uint_as_float(f2tf32(wd[i]));
    g_wu[i] = __uint_as_float(f2tf32(wu[i]));
}

// -------------------------------------------------------------------------
// TF32 tensor-core GEMM: out[b] = A(MxK) @ Bsrc[b](KxTT), fused epilogues.
// DOWN: B normalized on load (groupnorm) + mish + tf32-rounded h output.
// !DOWN: B via cp.async (pre-rounded h) + bias + residual.
// -------------------------------------------------------------------------
template <int M, int K, bool DOWN>
__global__ __launch_bounds__(256, 2)
void gemm_tc_kernel(const float* __restrict__ A,
                    const float* __restrict__ Bsrc,
                    const float* __restrict__ bias,
                    const float* __restrict__ resid,
                    float* __restrict__ out) {
    __shared__ float As[2][BM][ASTR];
    __shared__ float Bs[2][BK][BSTR];

    const int b  = blockIdx.z;
    const int m0 = blockIdx.y * BM;
    const int n0 = blockIdx.x * BN;
    const float* Bp = Bsrc + (size_t)b * K * TT;

    const int tid  = threadIdx.x;
    const int lane = tid & 31;
    const int wid  = tid >> 5;
    const int warp_m = wid >> 2;   // 0..1
    const int warp_n = wid & 3;    // 0..3
    const int grp = lane >> 2;     // 0..7
    const int lin = lane & 3;      // 0..3

    float acc[4][4][4];
#pragma unroll
    for (int i = 0; i < 4; i++)
#pragma unroll
        for (int j = 0; j < 4; j++)
#pragma unroll
            for (int r = 0; r < 4; r++) acc[i][j][r] = 0.f;

    const float* scale = g_scale + b * CC;
    const float* shift = g_shift + b * CC;

    // Global->smem mapping
    const int a_row = tid >> 2;   // 0..63 (+64 second pass)
    const int a_seg = tid & 3;    // k-seg of 4 floats
    const int b_row = tid >> 5;   // 0..7 (+8 second pass)
    const int b_c4  = tid & 31;   // n-seg of 4 floats

    float4 breg[2];
    float  bsc[2], bsh[2];

    // ---- prologue: stage 0 ----
    {
        cp_async16(&As[0][a_row][a_seg * 4],      A + (size_t)(m0 + a_row) * K + a_seg * 4);
        cp_async16(&As[0][a_row + 64][a_seg * 4], A + (size_t)(m0 + a_row + 64) * K + a_seg * 4);
        if (!DOWN) {
            cp_async16(&Bs[0][b_row][b_c4 * 4],     Bp + (size_t)b_row * TT + n0 + b_c4 * 4);
            cp_async16(&Bs[0][b_row + 8][b_c4 * 4], Bp + (size_t)(b_row + 8) * TT + n0 + b_c4 * 4);
        }
        CP_COMMIT();
        if (DOWN) {
            breg[0] = *(const float4*)(Bp + (size_t)b_row * TT + n0 + b_c4 * 4);
            breg[1] = *(const float4*)(Bp + (size_t)(b_row + 8) * TT + n0 + b_c4 * 4);
            bsc[0] = scale[b_row];     bsh[0] = shift[b_row];
            bsc[1] = scale[b_row + 8]; bsh[1] = shift[b_row + 8];
#pragma unroll
            for (int p = 0; p < 2; p++) {
                float4 v = breg[p];
                v.x = __uint_as_float(f2tf32(fmaf(v.x, bsc[p], bsh[p])));
                v.y = __uint_as_float(f2tf32(fmaf(v.y, bsc[p], bsh[p])));
                v.z = __uint_as_float(f2tf32(fmaf(v.z, bsc[p], bsh[p])));
                v.w = __uint_as_float(f2tf32(fmaf(v.w, bsc[p], bsh[p])));
                *(float4*)&Bs[0][b_row + p * 8][b_c4 * 4] = v;
            }
        }
        CP_WAIT_ALL();
        __syncthreads();
    }

    const int NIT = K / BK;
    for (int it = 0; it < NIT; ++it) {
        const int cur = it & 1, nxt = cur ^ 1;
        const bool more = (it + 1 < NIT);
        if (more) {
            const int k1 = (it + 1) * BK;
            cp_async16(&As[nxt][a_row][a_seg * 4],      A + (size_t)(m0 + a_row) * K + k1 + a_seg * 4);
            cp_async16(&As[nxt][a_row + 64][a_seg * 4], A + (size_t)(m0 + a_row + 64) * K + k1 + a_seg * 4);
            if (!DOWN) {
                cp_async16(&Bs[nxt][b_row][b_c4 * 4],     Bp + (size_t)(k1 + b_row) * TT + n0 + b_c4 * 4);
                cp_async16(&Bs[nxt][b_row + 8][b_c4 * 4], Bp + (size_t)(k1 + b_row + 8) * TT + n0 + b_c4 * 4);
            }
            CP_COMMIT();
            if (DOWN) {
                breg[0] = *(const float4*)(Bp + (size_t)(k1 + b_row) * TT + n0 + b_c4 * 4);
                breg[1] = *(const float4*)(Bp + (size_t)(k1 + b_row + 8) * TT + n0 + b_c4 * 4);
                bsc[0] = scale[k1 + b_row];     bsh[0] = shift[k1 + b_row];
                bsc[1] = scale[k1 + b_row + 8]; bsh[1] = shift[k1 + b_row + 8];
            }
        }

        // ---- compute on buffer cur ----
#pragma unroll
        for (int ks = 0; ks < BK / 8; ++ks) {
            const int k0 = ks * 8;
            uint32_t afr[4][4], bfr[4][2];
#pragma unroll
            for (int i = 0; i < 4; i++) {
                int mb = warp_m * 64 + i * 16;
                afr[i][0] = __float_as_uint(As[cur][mb + grp][k0 + lin]);
                afr[i][1] = __float_as_uint(As[cur][mb + grp + 8][k0 + lin]);
                afr[i][2] = __float_as_uint(As[cur][mb + grp][k0 + lin + 4]);
                afr[i][3] = __float_as_uint(As[cur][mb + grp + 8][k0 + lin + 4]);
            }
#pragma unroll
            for (int j = 0; j < 4; j++) {
                int nb = warp_n * 32 + j * 8;
                bfr[j][0] = __float_as_uint(Bs[cur][k0 + lin][nb + grp]);
                bfr[j][1] = __float_as_uint(Bs[cur][k0 + lin + 4][nb + grp]);
            }
#pragma unroll
            for (int i = 0; i < 4; i++)
#pragma unroll
                for (int j = 0; j < 4; j++)
                    mma_tf32(acc[i][j], afr[i], bfr[j]);
        }

        if (more) {
            if (DOWN) {
#pragma unroll
                for (int p = 0; p < 2; p++) {
                    float4 v = breg[p];
                    v.x = __uint_as_float(f2tf32(fmaf(v.x, bsc[p], bsh[p])));
                    v.y = __uint_as_float(f2tf32(fmaf(v.y, bsc[p], bsh[p])));
                    v.z = __uint_as_float(f2tf32(fmaf(v.z, bsc[p], bsh[p])));
                    v.w = __uint_as_float(f2tf32(fmaf(v.w, bsc[p], bsh[p])));
                    *(float4*)&Bs[nxt][b_row + p * 8][b_c4 * 4] = v;
                }
            }
            CP_WAIT_ALL();
        }
        __syncthreads();
    }

    // ---- epilogue ----
#pragma unroll
    for (int i = 0; i < 4; i++) {
        const int r0 = m0 + warp_m * 64 + i * 16 + grp;
        const float bv0 = bias[r0], bv1 = bias[r0 + 8];
#pragma unroll
        for (int j = 0; j < 4; j++) {
            const int c = n0 + warp_n * 32 + j * 8 + 2 * lin;
            const size_t o0 = ((size_t)b * M + r0) * TT + c;
            const size_t o1 = o0 + (size_t)8 * TT;
            float v0 = acc[i][j][0] + bv0, v1 = acc[i][j][1] + bv0;
            float v2 = acc[i][j][2] + bv1, v3 = acc[i][j][3] + bv1;
            if (DOWN) {
                v0 = __uint_as_float(f2tf32(mishf(v0)));
                v1 = __uint_as_float(f2tf32(mishf(v1)));
                v2 = __uint_as_float(f2tf32(mishf(v2)));
                v3 = __uint_as_float(f2tf32(mishf(v3)));
            } else {
                float2 ra = *(const float2*)(resid + o0);
                float2 rb = *(const float2*)(resid + o1);
                v0 += ra.x; v1 += ra.y; v2 += rb.x; v3 += rb.y;
            }
            *(float2*)(out + o0) = make_float2(v0, v1);
            *(float2*)(out + o1) = make_float2(v2, v3);
        }
    }
}

// -------------------------------------------------------------------------
extern "C" void kernel_launch(void* const* d_in, const int* in_sizes, int n_in,
                              void* d_out, int out_size) {
    const float* x      = (const float*)d_in[0];
    const float* gamma  = (const float*)d_in[1];
    const float* beta   = (const float*)d_in[2];
    const float* w_down = (const float*)d_in[3];
    const float* b_down = (const float*)d_in[4];
    const float* w_up   = (const float*)d_in[5];
    const float* b_up   = (const float*)d_in[6];
    float* out = (float*)d_out;

    float *h_ptr, *wd_ptr, *wu_ptr;
    cudaGetSymbolAddress((void**)&h_ptr,  g_h);
    cudaGetSymbolAddress((void**)&wd_ptr, g_wd);
    cudaGetSymbolAddress((void**)&wu_ptr, g_wu);

    gn_stats_kernel<<<BB * GG, 512>>>(x, gamma, beta);
    round_w_kernel<<<(CBOT * CC) / 256, 256>>>(w_down, w_up);

    // down: h = tf32(mish(w_down @ groupnorm(x) + b_down))
    gemm_tc_kernel<CBOT, CC, true>
        <<<dim3(TT / BN, CBOT / BM, BB), 256>>>(wd_ptr, x, b_down, nullptr, h_ptr);

    // up: out = w_up @ h + b_up + x
    gemm_tc_kernel<CC, CBOT, false>
        <<<dim3(TT / BN, CC / BM, BB), 256>>>(wu_ptr, h_ptr, b_up, x, out);
}

// round 4
// speedup vs baseline: 3.9924x; 1.4385x over previous
#include <cuda_runtime.h>
#include <cuda_fp16.h>
#include <math.h>
#include <stdint.h>

#define BB 64
#define CC 1024
#define TT 512
#define CBOT 256
#define GG 8
#define CPG 128
#define GN_EPS 1e-5f

#define BM 128
#define BN 128
#define BK 32            // fp16 k-depth per stage

// ---- scratch (__device__ globals: allocation-free rule) ----
__device__ __align__(256) __half g_h16[(size_t)BB * CBOT * TT];  // mish(down) [B,Cb,T]
__device__ __align__(256) __half g_wd16[CBOT * CC];
__device__ __align__(256) __half g_wu16[CC * CBOT];
__device__ float g_scale[BB * CC];
__device__ float g_shift[BB * CC];

// ---------------------------------------------------------------- helpers ----
__device__ __forceinline__ uint32_t smem_u32(const void* p) {
    return (uint32_t)__cvta_generic_to_shared(p);
}
__device__ __forceinline__ void cp_async16(uint32_t s, const void* g) {
    asm volatile("cp.async.cg.shared.global [%0], [%1], 16;" :: "r"(s), "l"(g));
}
#define CP_COMMIT()   asm volatile("cp.async.commit_group;")
#define CP_WAIT0()    asm volatile("cp.async.wait_group 0;")

// A smem: 128 m-rows x 32 halfs. Two m-rows share a 128B line (8 chunks of 16B).
// slot = ((m&1)*4 + c) ^ ((m>>1)&7)  -> conflict-free ldmatrix + writers.
__device__ __forceinline__ uint32_t a_addr(uint32_t base, int m, int c) {
    int slot = (((m & 1) << 2) | c) ^ ((m >> 1) & 7);
    return base + (m >> 1) * 128 + slot * 16;
}
// B smem: 32 k-rows x 128 halfs (256B rows, 16 chunks). slot = nc ^ (k&7).
__device__ __forceinline__ uint32_t b_addr(uint32_t base, int k, int nc) {
    int slot = nc ^ (k & 7);
    return base + k * 256 + slot * 16;
}

__device__ __forceinline__ void ldsm_x4(uint32_t* r, uint32_t addr) {
    asm volatile("ldmatrix.sync.aligned.m8n8.x4.shared.b16 {%0,%1,%2,%3}, [%4];"
                 : "=r"(r[0]), "=r"(r[1]), "=r"(r[2]), "=r"(r[3]) : "r"(addr));
}
__device__ __forceinline__ void ldsm_x4_t(uint32_t* r, uint32_t addr) {
    asm volatile("ldmatrix.sync.aligned.m8n8.x4.trans.shared.b16 {%0,%1,%2,%3}, [%4];"
                 : "=r"(r[0]), "=r"(r[1]), "=r"(r[2]), "=r"(r[3]) : "r"(addr));
}
__device__ __forceinline__ void mma16816(float* c, const uint32_t* a, const uint32_t* b) {
    asm volatile(
        "mma.sync.aligned.m16n8k16.row.col.f32.f16.f16.f32 "
        "{%0,%1,%2,%3}, {%4,%5,%6,%7}, {%8,%9}, {%0,%1,%2,%3};"
        : "+f"(c[0]), "+f"(c[1]), "+f"(c[2]), "+f"(c[3])
        : "r"(a[0]), "r"(a[1]), "r"(a[2]), "r"(a[3]), "r"(b[0]), "r"(b[1]));
}

__device__ __forceinline__ float mishf(float v) {
    if (v > 15.f) return v;
    float e = __expf(v);
    float w = (1.f + e) * (1.f + e);
    return v * (w - 1.f) / (w + 1.f);
}

// ---------------------------------------------------- GroupNorm statistics ----
__global__ void gn_stats_kernel(const float* __restrict__ x,
                                const float* __restrict__ gamma,
                                const float* __restrict__ beta) {
    int b = blockIdx.x >> 3, g = blockIdx.x & 7;
    const float4* xp = (const float4*)(x + ((size_t)b * CC + (size_t)g * CPG) * TT);
    const int N4 = CPG * TT / 4;
    float s = 0.f, ss = 0.f;
    for (int i = threadIdx.x; i < N4; i += 512) {
        float4 v = xp[i];
        s  += v.x + v.y + v.z + v.w;
        ss += v.x*v.x + v.y*v.y + v.z*v.z + v.w*v.w;
    }
#pragma unroll
    for (int o = 16; o; o >>= 1) {
        s  += __shfl_xor_sync(0xffffffffu, s, o);
        ss += __shfl_xor_sync(0xffffffffu, ss, o);
    }
    __shared__ float ws[16], wss[16];
    int w = threadIdx.x >> 5, l = threadIdx.x & 31;
    if (l == 0) { ws[w] = s; wss[w] = ss; }
    __syncthreads();
    if (threadIdx.x < CPG) {
        float S = 0.f, SS = 0.f;
#pragma unroll
        for (int i = 0; i < 16; i++) { S += ws[i]; SS += wss[i]; }
        float mean = S / 65536.f;
        float var  = SS / 65536.f - mean * mean;
        float rstd = rsqrtf(var + GN_EPS);
        int c = g * CPG + threadIdx.x;
        float sc = rstd * gamma[c];
        g_scale[b * CC + c] = sc;
        g_shift[b * CC + c] = beta[c] - mean * sc;
    }
}

// ------------------------------------------------ weights fp32 -> fp16 ----
__global__ void wconv_kernel(const float* __restrict__ wd,
                             const float* __restrict__ wu) {
    int i = blockIdx.x * 256 + threadIdx.x;
    g_wd16[i] = __float2half_rn(wd[i]);
    g_wu16[i] = __float2half_rn(wu[i]);
}

// -------------------------------------------------------------- GEMM -------
// out[b](MxTT) = A(MxK,fp16) @ B[b](KxTT)
// DOWN: B = groupnorm(x) fused on load (fp32 in), epilogue mish -> g_h16 fp16.
// !DOWN: B = g_h16 fp16 via cp.async, epilogue bias+residual -> fp32 out.
template <int M, int K, bool DOWN>
__global__ __launch_bounds__(256, 2)
void gemm_hmma(const __half* __restrict__ Ag, const void* __restrict__ Bg0,
               const float* __restrict__ bias, const float* __restrict__ resid,
               float* __restrict__ outp) {
    __shared__ __align__(256) char As[2][BM / 2 * 128];   // 8KB/stage
    __shared__ __align__(256) char Bs[2][BK * 256];       // 8KB/stage

    const int tid  = threadIdx.x;
    const int lane = tid & 31;
    const int wid  = tid >> 5;
    const int warp_m = wid >> 2;       // 0..1 -> 64 rows
    const int warp_n = wid & 3;        // 0..3 -> 32 cols
    const int grp = lane >> 2;
    const int lin = lane & 3;

    const int b  = blockIdx.z;
    const int m0 = blockIdx.y * BM;
    const int n0 = blockIdx.x * BN;

    const uint32_t as0 = smem_u32(As[0]), as1 = smem_u32(As[1]);
    const uint32_t bs0 = smem_u32(Bs[0]), bs1 = smem_u32(Bs[1]);

    const __half* Abase = Ag + (size_t)m0 * K;
    const float* scale = g_scale + b * CC;
    const float* shift = g_shift + b * CC;

    // ldmatrix lane geometry (constant across loop)
    const int lm_m = (lane & 7) + ((lane >> 3) & 1) * 8;  // row within 16
    const int lm_c = lane >> 4;                            // chunk parity

    // A writer mapping: chunk ids 2*tid, 2*tid+1 -> (m = id>>2, c = id&3)
    const int aw_m = tid >> 1;
    const int aw_c = (tid & 1) * 2;

    // DOWN B loader: lane-per-row (conflict-free STS)
    const int dk = tid & 31;           // k row
    const int dq = tid >> 5;           // 16-float group -> chunks 2dq, 2dq+1
    // UP B writer: chunk ids 2*tid,2*tid+1 -> (k = id>>4, nc = id&15)
    const int uk = tid >> 3;
    const int unc = (tid & 7) * 2;

    float acc[4][4][4];
#pragma unroll
    for (int i = 0; i < 4; i++)
#pragma unroll
        for (int j = 0; j < 4; j++)
#pragma unroll
            for (int r = 0; r < 4; r++) acc[i][j][r] = 0.f;

    float4 fb[4];     // DOWN B staging
    float fsc, fsh;

    // ---------------- prologue: stage 0 ----------------
    {
        cp_async16(a_addr(as0, aw_m, aw_c),     Abase + (size_t)aw_m * K + aw_c * 8);
        cp_async16(a_addr(as0, aw_m, aw_c + 1), Abase + (size_t)aw_m * K + aw_c * 8 + 8);
        if (DOWN) {
            const float* xr = (const float*)Bg0 + ((size_t)b * CC + dk) * TT + n0 + dq * 16;
            fb[0] = *(const float4*)(xr + 0);
            fb[1] = *(const float4*)(xr + 4);
            fb[2] = *(const float4*)(xr + 8);
            fb[3] = *(const float4*)(xr + 12);
            fsc = scale[dk]; fsh = shift[dk];
            uint4 pk0, pk1;
            __half2 h;
            h = __floats2half2_rn(fmaf(fb[0].x,fsc,fsh), fmaf(fb[0].y,fsc,fsh)); pk0.x = *(uint32_t*)&h;
            h = __floats2half2_rn(fmaf(fb[0].z,fsc,fsh), fmaf(fb[0].w,fsc,fsh)); pk0.y = *(uint32_t*)&h;
            h = __floats2half2_rn(fmaf(fb[1].x,fsc,fsh), fmaf(fb[1].y,fsc,fsh)); pk0.z = *(uint32_t*)&h;
            h = __floats2half2_rn(fmaf(fb[1].z,fsc,fsh), fmaf(fb[1].w,fsc,fsh)); pk0.w = *(uint32_t*)&h;
            h = __floats2half2_rn(fmaf(fb[2].x,fsc,fsh), fmaf(fb[2].y,fsc,fsh)); pk1.x = *(uint32_t*)&h;
            h = __floats2half2_rn(fmaf(fb[2].z,fsc,fsh), fmaf(fb[2].w,fsc,fsh)); pk1.y = *(uint32_t*)&h;
            h = __floats2half2_rn(fmaf(fb[3].x,fsc,fsh), fmaf(fb[3].y,fsc,fsh)); pk1.z = *(uint32_t*)&h;
            h = __floats2half2_rn(fmaf(fb[3].z,fsc,fsh), fmaf(fb[3].w,fsc,fsh)); pk1.w = *(uint32_t*)&h;
            *(uint4*)(Bs[0] + (b_addr(bs0, dk, dq * 2) - bs0))     = pk0;
            *(uint4*)(Bs[0] + (b_addr(bs0, dk, dq * 2 + 1) - bs0)) = pk1;
        } else {
            const __half* hb = (const __half*)Bg0 + (size_t)b * K * TT;
            cp_async16(b_addr(bs0, uk, unc),     hb + (size_t)uk * TT + n0 + unc * 8);
            cp_async16(b_addr(bs0, uk, unc + 1), hb + (size_t)uk * TT + n0 + unc * 8 + 8);
        }
        CP_COMMIT();
        CP_WAIT0();
        __syncthreads();
    }

    const int NIT = K / BK;
    for (int it = 0; it < NIT; ++it) {
        const uint32_t asc = (it & 1) ? as1 : as0;
        const uint32_t bsc = (it & 1) ? bs1 : bs0;
        const uint32_t asn = (it & 1) ? as0 : as1;
        const uint32_t bsn = (it & 1) ? bs0 : bs1;
        const bool more = (it + 1 < NIT);

        if (more) {
            const int k1 = (it + 1) * BK;
            cp_async16(a_addr(asn, aw_m, aw_c),     Abase + (size_t)aw_m * K + k1 + aw_c * 8);
            cp_async16(a_addr(asn, aw_m, aw_c + 1), Abase + (size_t)aw_m * K + k1 + aw_c * 8 + 8);
            if (!DOWN) {
                const __half* hb = (const __half*)Bg0 + (size_t)b * K * TT;
                cp_async16(b_addr(bsn, uk, unc),     hb + (size_t)(k1 + uk) * TT + n0 + unc * 8);
                cp_async16(b_addr(bsn, uk, unc + 1), hb + (size_t)(k1 + uk) * TT + n0 + unc * 8 + 8);
            }
            CP_COMMIT();
            if (DOWN) {
                const float* xr = (const float*)Bg0 + ((size_t)b * CC + k1 + dk) * TT + n0 + dq * 16;
                fb[0] = *(const float4*)(xr + 0);
                fb[1] = *(const float4*)(xr + 4);
                fb[2] = *(const float4*)(xr + 8);
                fb[3] = *(const float4*)(xr + 12);
                fsc = scale[k1 + dk]; fsh = shift[k1 + dk];
            }
        }

        // ---------------- compute on current buffers ----------------
#pragma unroll
        for (int ks = 0; ks < 2; ++ks) {
            uint32_t a[4][4], bf[2][4];
#pragma unroll
            for (int i = 0; i < 4; i++)
                ldsm_x4(a[i], a_addr(asc, warp_m * 64 + i * 16 + lm_m, ks * 2 + lm_c));
#pragma unroll
            for (int p = 0; p < 2; p++)
                ldsm_x4_t(bf[p], b_addr(bsc, ks * 16 + lm_m, warp_n * 4 + p * 2 + lm_c));
#pragma unroll
            for (int i = 0; i < 4; i++)
#pragma unroll
                for (int j = 0; j < 4; j++)
                    mma16816(acc[i][j], a[i], &bf[j >> 1][(j & 1) * 2]);
        }

        if (more) {
            if (DOWN) {
                uint4 pk0, pk1;
                __half2 h;
                h = __floats2half2_rn(fmaf(fb[0].x,fsc,fsh), fmaf(fb[0].y,fsc,fsh)); pk0.x = *(uint32_t*)&h;
                h = __floats2half2_rn(fmaf(fb[0].z,fsc,fsh), fmaf(fb[0].w,fsc,fsh)); pk0.y = *(uint32_t*)&h;
                h = __floats2half2_rn(fmaf(fb[1].x,fsc,fsh), fmaf(fb[1].y,fsc,fsh)); pk0.z = *(uint32_t*)&h;
                h = __floats2half2_rn(fmaf(fb[1].z,fsc,fsh), fmaf(fb[1].w,fsc,fsh)); pk0.w = *(uint32_t*)&h;
                h = __floats2half2_rn(fmaf(fb[2].x,fsc,fsh), fmaf(fb[2].y,fsc,fsh)); pk1.x = *(uint32_t*)&h;
                h = __floats2half2_rn(fmaf(fb[2].z,fsc,fsh), fmaf(fb[2].w,fsc,fsh)); pk1.y = *(uint32_t*)&h;
                h = __floats2half2_rn(fmaf(fb[3].x,fsc,fsh), fmaf(fb[3].y,fsc,fsh)); pk1.z = *(uint32_t*)&h;
                h = __floats2half2_rn(fmaf(fb[3].z,fsc,fsh), fmaf(fb[3].w,fsc,fsh)); pk1.w = *(uint32_t*)&h;
                char* bsn_p = (it & 1) ? Bs[0] : Bs[1];
                *(uint4*)(bsn_p + (b_addr(bsn, dk, dq * 2) - bsn))     = pk0;
                *(uint4*)(bsn_p + (b_addr(bsn, dk, dq * 2 + 1) - bsn)) = pk1;
            }
            CP_WAIT0();
        }
        __syncthreads();
    }

    // ---------------- epilogue ----------------
#pragma unroll
    for (int i = 0; i < 4; i++) {
        const int r0 = m0 + warp_m * 64 + i * 16 + grp;
        const float bv0 = bias[r0], bv1 = bias[r0 + 8];
        if (DOWN) {
            __half* hp0 = g_h16 + ((size_t)b * M + r0) * TT;
            __half* hp1 = hp0 + (size_t)8 * TT;
#pragma unroll
            for (int j = 0; j < 4; j++) {
                const int c = n0 + warp_n * 32 + j * 8 + 2 * lin;
                __half2 v0 = __floats2half2_rn(mishf(acc[i][j][0] + bv0),
                                               mishf(acc[i][j][1] + bv0));
                __half2 v1 = __floats2half2_rn(mishf(acc[i][j][2] + bv1),
                                               mishf(acc[i][j][3] + bv1));
                *(__half2*)(hp0 + c) = v0;
                *(__half2*)(hp1 + c) = v1;
            }
        } else {
#pragma unroll
            for (int j = 0; j < 4; j++) {
                const int c = n0 + warp_n * 32 + j * 8 + 2 * lin;
                const size_t o0 = ((size_t)b * M + r0) * TT + c;
                const size_t o1 = o0 + (size_t)8 * TT;
                float2 ra = *(const float2*)(resid + o0);
                float2 rb = *(const float2*)(resid + o1);
                *(float2*)(outp + o0) = make_float2(acc[i][j][0] + bv0 + ra.x,
                                                    acc[i][j][1] + bv0 + ra.y);
                *(float2*)(outp + o1) = make_float2(acc[i][j][2] + bv1 + rb.x,
                                                    acc[i][j][3] + bv1 + rb.y);
            }
        }
    }
}

// ---------------------------------------------------------------- launch ----
extern "C" void kernel_launch(void* const* d_in, const int* in_sizes, int n_in,
                              void* d_out, int out_size) {
    const float* x      = (const float*)d_in[0];
    const float* gamma  = (const float*)d_in[1];
    const float* beta   = (const float*)d_in[2];
    const float* w_down = (const float*)d_in[3];
    const float* b_down = (const float*)d_in[4];
    const float* w_up   = (const float*)d_in[5];
    const float* b_up   = (const float*)d_in[6];
    float* out = (float*)d_out;

    __half *h16, *wd16, *wu16;
    cudaGetSymbolAddress((void**)&h16,  g_h16);
    cudaGetSymbolAddress((void**)&wd16, g_wd16);
    cudaGetSymbolAddress((void**)&wu16, g_wu16);

    gn_stats_kernel<<<BB * GG, 512>>>(x, gamma, beta);
    wconv_kernel<<<(CBOT * CC) / 256, 256>>>(w_down, w_up);

    // down: h = mish(w_down @ groupnorm(x) + b_down)   [B,Cb,T] fp16
    gemm_hmma<CBOT, CC, true>
        <<<dim3(TT / BN, CBOT / BM, BB), 256>>>(wd16, x, b_down, nullptr, nullptr);

    // up: out = w_up @ h + b_up + x
    gemm_hmma<CC, CBOT, false>
        <<<dim3(TT / BN, CC / BM, BB), 256>>>(wu16, h16, b_up, x, out);
}

// round 5
// speedup vs baseline: 4.1570x; 1.0412x over previous
#include <cuda_runtime.h>
#include <cuda_fp16.h>
#include <math.h>
#include <stdint.h>

#define BB 64
#define CC 1024
#define TT 512
#define CBOT 256
#define GG 8
#define CPG 128
#define GN_EPS 1e-5f

#define BM 128
#define BN 256
#define BK 32
#define NSTAGE 3
#define A_STAGE 8192            // 128 rows x 32 halfs
#define B_STAGE 16384           // 32 rows x 256 halfs
#define SMEM_TOTAL (NSTAGE * (A_STAGE + B_STAGE))   // 73728

// ---- scratch (__device__ globals: allocation-free rule) ----
__device__ __align__(256) __half g_x16[(size_t)BB * CC * TT];    // groupnorm(x) fp16 [B,C,T]
__device__ __align__(256) __half g_h16[(size_t)BB * CBOT * TT];  // mish(down)   fp16 [B,Cb,T]
__device__ __align__(256) __half g_wd16[CBOT * CC];
__device__ __align__(256) __half g_wu16[CC * CBOT];

// ---------------------------------------------------------------- helpers ----
__device__ __forceinline__ uint32_t smem_u32(const void* p) {
    return (uint32_t)__cvta_generic_to_shared(p);
}
__device__ __forceinline__ void cp_async16(uint32_t s, const void* g) {
    asm volatile("cp.async.cg.shared.global [%0], [%1], 16;" :: "r"(s), "l"(g));
}
#define CP_COMMIT()  asm volatile("cp.async.commit_group;")
#define CP_WAIT(n)   asm volatile("cp.async.wait_group %0;" :: "n"(n))

// A smem: 128 m-rows x 32 halfs; two m-rows per 128B line.
// slot = ((m&1)*4 + c) ^ ((m>>1)&7): conflict-free for writers + ldmatrix.
__device__ __forceinline__ uint32_t a_addr(uint32_t base, int m, int c) {
    int slot = (((m & 1) << 2) | c) ^ ((m >> 1) & 7);
    return base + (m >> 1) * 128 + slot * 16;
}
// B smem: 32 k-rows x 256 halfs (512B rows, 32 chunks of 16B).
// slot = nc with low 3 bits XOR'd by (k&7): conflict-free.
__device__ __forceinline__ uint32_t b_addr(uint32_t base, int k, int nc) {
    int slot = (nc & 24) | ((nc ^ k) & 7);
    return base + k * 512 + slot * 16;
}

__device__ __forceinline__ void ldsm_x4(uint32_t* r, uint32_t addr) {
    asm volatile("ldmatrix.sync.aligned.m8n8.x4.shared.b16 {%0,%1,%2,%3}, [%4];"
                 : "=r"(r[0]), "=r"(r[1]), "=r"(r[2]), "=r"(r[3]) : "r"(addr));
}
__device__ __forceinline__ void ldsm_x4_t(uint32_t* r, uint32_t addr) {
    asm volatile("ldmatrix.sync.aligned.m8n8.x4.trans.shared.b16 {%0,%1,%2,%3}, [%4];"
                 : "=r"(r[0]), "=r"(r[1]), "=r"(r[2]), "=r"(r[3]) : "r"(addr));
}
__device__ __forceinline__ void mma16816(float* c, const uint32_t* a, const uint32_t* b) {
    asm volatile(
        "mma.sync.aligned.m16n8k16.row.col.f32.f16.f16.f32 "
        "{%0,%1,%2,%3}, {%4,%5,%6,%7}, {%8,%9}, {%0,%1,%2,%3};"
        : "+f"(c[0]), "+f"(c[1]), "+f"(c[2]), "+f"(c[3])
        : "r"(a[0]), "r"(a[1]), "r"(a[2]), "r"(a[3]), "r"(b[0]), "r"(b[1]));
}
__device__ __forceinline__ float mishf(float v) {
    if (v > 15.f) return v;
    float e = __expf(v);
    float w = (1.f + e) * (1.f + e);
    return v * (w - 1.f) / (w + 1.f);
}

// ---------------- GroupNorm: stats + normalize + fp16 store, one kernel ----
__global__ __launch_bounds__(512)
void gn_norm_kernel(const float* __restrict__ x,
                    const float* __restrict__ gamma,
                    const float* __restrict__ beta) {
    int b = blockIdx.x >> 3, g = blockIdx.x & 7;
    const size_t base = ((size_t)b * CC + (size_t)g * CPG) * TT;
    const float4* xp = (const float4*)(x + base);
    const int N4 = CPG * TT / 4;   // 16384
    float s = 0.f, ss = 0.f;
#pragma unroll 4
    for (int i = threadIdx.x; i < N4; i += 512) {
        float4 v = xp[i];
        s  += v.x + v.y + v.z + v.w;
        ss += v.x*v.x + v.y*v.y + v.z*v.z + v.w*v.w;
    }
#pragma unroll
    for (int o = 16; o; o >>= 1) {
        s  += __shfl_xor_sync(0xffffffffu, s, o);
        ss += __shfl_xor_sync(0xffffffffu, ss, o);
    }
    __shared__ float ws[16], wss[16];
    __shared__ float s_sc[CPG], s_sh[CPG];
    int w = threadIdx.x >> 5, l = threadIdx.x & 31;
    if (l == 0) { ws[w] = s; wss[w] = ss; }
    __syncthreads();
    if (threadIdx.x < CPG) {
        float S = 0.f, SS = 0.f;
#pragma unroll
        for (int i = 0; i < 16; i++) { S += ws[i]; SS += wss[i]; }
        float mean = S / 65536.f;
        float var  = SS / 65536.f - mean * mean;
        float rstd = rsqrtf(var + GN_EPS);
        int c = g * CPG + threadIdx.x;
        float sc = rstd * gamma[c];
        s_sc[threadIdx.x] = sc;
        s_sh[threadIdx.x] = beta[c] - mean * sc;
    }
    __syncthreads();
    uint2* op = (uint2*)(g_x16 + base);
#pragma unroll 4
    for (int i = threadIdx.x; i < N4; i += 512) {
        int c = i >> 7;                    // 128 float4 per channel row
        float4 v = xp[i];
        float sc = s_sc[c], sh = s_sh[c];
        __half2 h0 = __floats2half2_rn(fmaf(v.x, sc, sh), fmaf(v.y, sc, sh));
        __half2 h1 = __floats2half2_rn(fmaf(v.z, sc, sh), fmaf(v.w, sc, sh));
        uint2 pk;
        pk.x = *(uint32_t*)&h0;
        pk.y = *(uint32_t*)&h1;
        op[i] = pk;
    }
}

// ------------------------------------------------ weights fp32 -> fp16 ----
__global__ void wconv_kernel(const float* __restrict__ wd,
                             const float* __restrict__ wu) {
    int i = blockIdx.x * 256 + threadIdx.x;
    g_wd16[i] = __float2half_rn(wd[i]);
    g_wu16[i] = __float2half_rn(wu[i]);
}

// -------------------------------------------------------------- GEMM -------
// out[b](MxTT) = A(MxK,fp16) @ B[b](KxTT,fp16)
// CTA tile 128x256, 8 warps (2x4) of 64x64, 3-stage cp.async ring.
// DOWN: epilogue mish -> g_h16 fp16.  !DOWN: bias + residual -> fp32 out.
template <int M, int K, bool DOWN>
__global__ __launch_bounds__(256, 1)
void gemm_hmma(const __half* __restrict__ Ag, const __half* __restrict__ Bg0,
               const float* __restrict__ bias, const float* __restrict__ resid,
               float* __restrict__ outp) {
    extern __shared__ __align__(1024) char smem_raw[];
    const uint32_t sA = smem_u32(smem_raw);
    const uint32_t sB = sA + NSTAGE * A_STAGE;

    const int tid  = threadIdx.x;
    const int lane = tid & 31;
    const int wid  = tid >> 5;
    const int warp_m = wid >> 2;       // 0..1
    const int warp_n = wid & 3;        // 0..3
    const int grp = lane >> 2;
    const int lin = lane & 3;

    const int b  = blockIdx.z;
    const int m0 = blockIdx.y * BM;
    const int n0 = blockIdx.x * BN;

    const __half* Abase = Ag + (size_t)m0 * K;
    const __half* Bbase = Bg0 + (size_t)b * K * TT + n0;

    // ldmatrix lane geometry
    const int lm_m = (lane & 7) + ((lane >> 3) & 1) * 8;
    const int lm_c = lane >> 4;

    // writer mappings
    const int aw_m = tid >> 1;
    const int aw_c = (tid & 1) * 2;
    const int uk  = tid >> 3;          // 0..31
    const int unc = (tid & 7) * 4;     // 0,4,...,28

    float acc[4][8][4];
#pragma unroll
    for (int i = 0; i < 4; i++)
#pragma unroll
        for (int j = 0; j < 8; j++)
#pragma unroll
            for (int r = 0; r < 4; r++) acc[i][j][r] = 0.f;

    const int NIT = K / BK;

    // ---- prologue: stages 0,1 ----
#pragma unroll
    for (int s = 0; s < NSTAGE - 1; s++) {
        const int k0 = s * BK;
        const uint32_t da = sA + s * A_STAGE;
        const uint32_t db = sB + s * B_STAGE;
        cp_async16(a_addr(da, aw_m, aw_c),     Abase + (size_t)aw_m * K + k0 + aw_c * 8);
        cp_async16(a_addr(da, aw_m, aw_c + 1), Abase + (size_t)aw_m * K + k0 + aw_c * 8 + 8);
#pragma unroll
        for (int i = 0; i < 4; i++)
            cp_async16(b_addr(db, uk, unc + i), Bbase + (size_t)(k0 + uk) * TT + (unc + i) * 8);
        CP_COMMIT();
    }
    CP_WAIT(1);
    __syncthreads();

    for (int it = 0; it < NIT; ++it) {
        // issue loads for stage it+2 (overwrites stage consumed at it-1;
        // the trailing __syncthreads of it-1 protects it)
        const int j = it + NSTAGE - 1;
        if (j < NIT) {
            const int st = j % NSTAGE;
            const int k0 = j * BK;
            const uint32_t da = sA + st * A_STAGE;
            const uint32_t db = sB + st * B_STAGE;
            cp_async16(a_addr(da, aw_m, aw_c),     Abase + (size_t)aw_m * K + k0 + aw_c * 8);
            cp_async16(a_addr(da, aw_m, aw_c + 1), Abase + (size_t)aw_m * K + k0 + aw_c * 8 + 8);
#pragma unroll
            for (int i = 0; i < 4; i++)
                cp_async16(b_addr(db, uk, unc + i), Bbase + (size_t)(k0 + uk) * TT + (unc + i) * 8);
        }
        CP_COMMIT();

        // compute stage it
        const int cs = it % NSTAGE;
        const uint32_t ca = sA + cs * A_STAGE;
        const uint32_t cb = sB + cs * B_STAGE;
#pragma unroll
        for (int ks = 0; ks < 2; ++ks) {
            uint32_t a[4][4], bf[4][4];
#pragma unroll
            for (int i = 0; i < 4; i++)
                ldsm_x4(a[i], a_addr(ca, warp_m * 64 + i * 16 + lm_m, ks * 2 + lm_c));
#pragma unroll
            for (int p = 0; p < 4; p++)
                ldsm_x4_t(bf[p], b_addr(cb, ks * 16 + lm_m, warp_n * 8 + p * 2 + lm_c));
#pragma unroll
            for (int i = 0; i < 4; i++)
#pragma unroll
                for (int j2 = 0; j2 < 8; j2++)
                    mma16816(acc[i][j2], a[i], &bf[j2 >> 1][(j2 & 1) * 2]);
        }

        // ensure stage it+1 is resident before next iter's compute
        CP_WAIT(1);
        __syncthreads();
    }

    // ---------------- epilogue ----------------
#pragma unroll
    for (int i = 0; i < 4; i++) {
        const int r0 = m0 + warp_m * 64 + i * 16 + grp;
        const float bv0 = bias[r0], bv1 = bias[r0 + 8];
        if (DOWN) {
            __half* hp0 = g_h16 + ((size_t)b * M + r0) * TT;
            __half* hp1 = hp0 + (size_t)8 * TT;
#pragma unroll
            for (int j = 0; j < 8; j++) {
                const int c = n0 + warp_n * 64 + j * 8 + 2 * lin;
                __half2 v0 = __floats2half2_rn(mishf(acc[i][j][0] + bv0),
                                               mishf(acc[i][j][1] + bv0));
                __half2 v1 = __floats2half2_rn(mishf(acc[i][j][2] + bv1),
                                               mishf(acc[i][j][3] + bv1));
                *(__half2*)(hp0 + c) = v0;
                *(__half2*)(hp1 + c) = v1;
            }
        } else {
#pragma unroll
            for (int j = 0; j < 8; j++) {
                const int c = n0 + warp_n * 64 + j * 8 + 2 * lin;
                const size_t o0 = ((size_t)b * M + r0) * TT + c;
                const size_t o1 = o0 + (size_t)8 * TT;
                float2 ra = *(const float2*)(resid + o0);
                float2 rb = *(const float2*)(resid + o1);
                *(float2*)(outp + o0) = make_float2(acc[i][j][0] + bv0 + ra.x,
                                                    acc[i][j][1] + bv0 + ra.y);
                *(float2*)(outp + o1) = make_float2(acc[i][j][2] + bv1 + rb.x,
                                                    acc[i][j][3] + bv1 + rb.y);
            }
        }
    }
}

// ---------------------------------------------------------------- launch ----
extern "C" void kernel_launch(void* const* d_in, const int* in_sizes, int n_in,
                              void* d_out, int out_size) {
    const float* x      = (const float*)d_in[0];
    const float* gamma  = (const float*)d_in[1];
    const float* beta   = (const float*)d_in[2];
    const float* w_down = (const float*)d_in[3];
    const float* b_down = (const float*)d_in[4];
    const float* w_up   = (const float*)d_in[5];
    const float* b_up   = (const float*)d_in[6];
    float* out = (float*)d_out;

    __half *x16, *h16, *wd16, *wu16;
    cudaGetSymbolAddress((void**)&x16,  g_x16);
    cudaGetSymbolAddress((void**)&h16,  g_h16);
    cudaGetSymbolAddress((void**)&wd16, g_wd16);
    cudaGetSymbolAddress((void**)&wu16, g_wu16);

    cudaFuncSetAttribute(gemm_hmma<CBOT, CC, true>,
                         cudaFuncAttributeMaxDynamicSharedMemorySize, SMEM_TOTAL);
    cudaFuncSetAttribute(gemm_hmma<CC, CBOT, false>,
                         cudaFuncAttributeMaxDynamicSharedMemorySize, SMEM_TOTAL);

    gn_norm_kernel<<<BB * GG, 512>>>(x, gamma, beta);
    wconv_kernel<<<(CBOT * CC) / 256, 256>>>(w_down, w_up);

    // down: h = mish(w_down @ xn + b_down)   [B,Cb,T] fp16
    gemm_hmma<CBOT, CC, true>
        <<<dim3(TT / BN, CBOT / BM, BB), 256, SMEM_TOTAL>>>(
            wd16, x16, b_down, nullptr, nullptr);

    // up: out = w_up @ h + b_up + x
    gemm_hmma<CC, CBOT, false>
        <<<dim3(TT / BN, CC / BM, BB), 256, SMEM_TOTAL>>>(
            wu16, h16, b_up, x, out);
}

// round 6
// speedup vs baseline: 4.3437x; 1.0449x over previous
#include <cuda_runtime.h>
#include <cuda_fp16.h>
#include <math.h>
#include <stdint.h>

#define BB 64
#define CC 1024
#define TT 512
#define CBOT 256
#define GG 8
#define CPG 128
#define GN_EPS 1e-5f

// megakernel tiling: CTA = (b, 128-t block); 8 warps (2m x 4n) of 64x32
#define TB 128                   // t per CTA
#define BK 32
#define A_STAGE 8192             // 128 rows x 32 halfs
#define B_STAGE 8192             // 32 rows x 128 halfs
#define HS_BYTES 65536           // h tile: 256 x 128 fp16 (swizzled rows of 256B)
#define SMEM_MEGA (HS_BYTES + 3 * (A_STAGE + B_STAGE))   // 114688
#define SMEM_GN   131072         // fp16 stash of one group slice

// ---- scratch (__device__ globals: allocation-free rule) ----
__device__ __align__(256) __half g_x16[(size_t)BB * CC * TT];  // groupnorm(x) fp16 [B,C,T]
__device__ __align__(256) __half g_wd16[CBOT * CC];
__device__ __align__(256) __half g_wu16[CC * CBOT];

// ---------------------------------------------------------------- helpers ----
__device__ __forceinline__ uint32_t smem_u32(const void* p) {
    return (uint32_t)__cvta_generic_to_shared(p);
}
__device__ __forceinline__ void cp_async16(uint32_t s, const void* g) {
    asm volatile("cp.async.cg.shared.global [%0], [%1], 16;" :: "r"(s), "l"(g));
}
#define CP_COMMIT()  asm volatile("cp.async.commit_group;")
#define CP_WAIT1()   asm volatile("cp.async.wait_group 1;")

// A smem: 128 m-rows x 32 halfs; two m-rows per 128B line.
__device__ __forceinline__ uint32_t a_addr(uint32_t base, int m, int c) {
    int slot = (((m & 1) << 2) | c) ^ ((m >> 1) & 7);
    return base + (m >> 1) * 128 + slot * 16;
}
// B/h smem: k-rows of 128 halfs (256B, 16 chunks); slot = nc ^ (k&7).
__device__ __forceinline__ uint32_t b_addr(uint32_t base, int k, int nc) {
    int slot = nc ^ (k & 7);
    return base + k * 256 + slot * 16;
}

__device__ __forceinline__ void ldsm_x4(uint32_t* r, uint32_t addr) {
    asm volatile("ldmatrix.sync.aligned.m8n8.x4.shared.b16 {%0,%1,%2,%3}, [%4];"
                 : "=r"(r[0]), "=r"(r[1]), "=r"(r[2]), "=r"(r[3]) : "r"(addr));
}
__device__ __forceinline__ void ldsm_x4_t(uint32_t* r, uint32_t addr) {
    asm volatile("ldmatrix.sync.aligned.m8n8.x4.trans.shared.b16 {%0,%1,%2,%3}, [%4];"
                 : "=r"(r[0]), "=r"(r[1]), "=r"(r[2]), "=r"(r[3]) : "r"(addr));
}
__device__ __forceinline__ void mma16816(float* c, const uint32_t* a, const uint32_t* b) {
    asm volatile(
        "mma.sync.aligned.m16n8k16.row.col.f32.f16.f16.f32 "
        "{%0,%1,%2,%3}, {%4,%5,%6,%7}, {%8,%9}, {%0,%1,%2,%3};"
        : "+f"(c[0]), "+f"(c[1]), "+f"(c[2]), "+f"(c[3])
        : "r"(a[0]), "r"(a[1]), "r"(a[2]), "r"(a[3]), "r"(b[0]), "r"(b[1]));
}
__device__ __forceinline__ float mishf(float v) {
    if (v > 15.f) return v;
    float e = __expf(v);
    float w = (1.f + e) * (1.f + e);
    return v * (w - 1.f) / (w + 1.f);
}

// shared 32-k-slice compute: A frags from stage ca, B frags from cbBase+kbase
__device__ __forceinline__ void compute_k32(float acc[4][4][4], uint32_t ca,
                                            uint32_t cbBase, int kbase,
                                            int warp_m, int warp_n,
                                            int lm_m, int lm_c) {
#pragma unroll
    for (int ks = 0; ks < 2; ++ks) {
        uint32_t a[4][4], bf[2][4];
#pragma unroll
        for (int i = 0; i < 4; i++)
            ldsm_x4(a[i], a_addr(ca, warp_m * 64 + i * 16 + lm_m, ks * 2 + lm_c));
#pragma unroll
        for (int p = 0; p < 2; p++)
            ldsm_x4_t(bf[p], b_addr(cbBase, kbase + ks * 16 + lm_m,
                                    warp_n * 4 + p * 2 + lm_c));
#pragma unroll
        for (int i = 0; i < 4; i++)
#pragma unroll
            for (int j = 0; j < 4; j++)
                mma16816(acc[i][j], a[i], &bf[j >> 1][(j & 1) * 2]);
    }
}

// ---------------- GroupNorm: single-pass via fp16 smem stash ----------------
__global__ __launch_bounds__(512)
void gn_norm_kernel(const float* __restrict__ x,
                    const float* __restrict__ gamma,
                    const float* __restrict__ beta) {
    extern __shared__ __align__(16) char sraw[];
    uint2* stash = (uint2*)sraw;                 // 16384 uint2 = 128KB
    __shared__ float ws[16], wss[16], s_sc[CPG], s_sh[CPG];

    int b = blockIdx.x >> 3, g = blockIdx.x & 7;
    const size_t base = ((size_t)b * CC + (size_t)g * CPG) * TT;
    const float4* xp = (const float4*)(x + base);
    const int N4 = CPG * TT / 4;                 // 16384

    float s = 0.f, ss = 0.f;
#pragma unroll 4
    for (int i = threadIdx.x; i < N4; i += 512) {
        float4 v = xp[i];
        s  += v.x + v.y + v.z + v.w;
        ss += v.x*v.x + v.y*v.y + v.z*v.z + v.w*v.w;
        __half2 h0 = __floats2half2_rn(v.x, v.y);
        __half2 h1 = __floats2half2_rn(v.z, v.w);
        uint2 pk;
        pk.x = *(uint32_t*)&h0;
        pk.y = *(uint32_t*)&h1;
        stash[i] = pk;
    }
#pragma unroll
    for (int o = 16; o; o >>= 1) {
        s  += __shfl_xor_sync(0xffffffffu, s, o);
        ss += __shfl_xor_sync(0xffffffffu, ss, o);
    }
    int w = threadIdx.x >> 5, l = threadIdx.x & 31;
    if (l == 0) { ws[w] = s; wss[w] = ss; }
    __syncthreads();
    if (threadIdx.x < CPG) {
        float S = 0.f, SS = 0.f;
#pragma unroll
        for (int i = 0; i < 16; i++) { S += ws[i]; SS += wss[i]; }
        float mean = S / 65536.f;
        float var  = SS / 65536.f - mean * mean;
        float rstd = rsqrtf(var + GN_EPS);
        int c = g * CPG + threadIdx.x;
        float sc = rstd * gamma[c];
        s_sc[threadIdx.x] = sc;
        s_sh[threadIdx.x] = beta[c] - mean * sc;
    }
    __syncthreads();
    uint2* op = (uint2*)(g_x16 + base);
#pragma unroll 4
    for (int i = threadIdx.x; i < N4; i += 512) {
        uint2 pk = stash[i];
        int c = i >> 7;
        float sc = s_sc[c], sh = s_sh[c];
        __half2 h0 = *(__half2*)&pk.x;
        __half2 h1 = *(__half2*)&pk.y;
        float2 f0 = __half22float2(h0);
        float2 f1 = __half22float2(h1);
        __half2 o0 = __floats2half2_rn(fmaf(f0.x, sc, sh), fmaf(f0.y, sc, sh));
        __half2 o1 = __floats2half2_rn(fmaf(f1.x, sc, sh), fmaf(f1.y, sc, sh));
        uint2 po;
        po.x = *(uint32_t*)&o0;
        po.y = *(uint32_t*)&o1;
        op[i] = po;
    }
}

// ------------------------------------------------ weights fp32 -> fp16 ----
__global__ void wconv_kernel(const float* __restrict__ wd,
                             const float* __restrict__ wu) {
    int i = blockIdx.x * 256 + threadIdx.x;
    g_wd16[i] = __float2half_rn(wd[i]);
    g_wu16[i] = __float2half_rn(wu[i]);
}

// ------------------------------- fused down+up megakernel -------------------
// CTA = (t-block tb, batch b). Phase 1: hS[256][128] = mish(w_down@xn+b_down)
// in smem (two 128-row halves). Phase 2: 8 m-tiles of out = w_up@hS + b_up + x.
__global__ __launch_bounds__(256, 2)
void mega_kernel(const float* __restrict__ xres,
                 const float* __restrict__ b_down,
                 const float* __restrict__ b_up,
                 float* __restrict__ outp) {
    extern __shared__ __align__(1024) char smem_raw[];
    const uint32_t hS = smem_u32(smem_raw);
    const uint32_t sA = hS + HS_BYTES;
    const uint32_t sB = sA + 3 * A_STAGE;

    const int tid  = threadIdx.x;
    const int lane = tid & 31;
    const int wid  = tid >> 5;
    const int warp_m = wid >> 2;
    const int warp_n = wid & 3;
    const int grp = lane >> 2;
    const int lin = lane & 3;
    const int lm_m = (lane & 7) + ((lane >> 3) & 1) * 8;
    const int lm_c = lane >> 4;

    const int tb = blockIdx.x;     // 0..3
    const int b  = blockIdx.y;     // 0..63
    const int t0 = tb * TB;

    // writer lane mappings
    const int aw_m = tid >> 1;
    const int aw_c = (tid & 1) * 2;
    const int bw_k = tid >> 3;
    const int bw_nc = (tid & 7) * 2;

    float acc[4][4][4];

    // ======================= PHASE 1: h tile =======================
    const __half* Bb = g_x16 + (size_t)b * CC * TT + t0;   // [k=c][t], stride TT

#pragma unroll 1
    for (int hh = 0; hh < 2; ++hh) {
        const __half* Ab = g_wd16 + (size_t)hh * 128 * CC;
#pragma unroll
        for (int i = 0; i < 4; i++)
#pragma unroll
            for (int j = 0; j < 4; j++)
#pragma unroll
                for (int r = 0; r < 4; r++) acc[i][j][r] = 0.f;

        // prologue: stages 0,1
#pragma unroll
        for (int sst = 0; sst < 2; ++sst) {
            const int k0 = sst * BK;
            const uint32_t da = sA + sst * A_STAGE;
            const uint32_t db = sB + sst * B_STAGE;
            cp_async16(a_addr(da, aw_m, aw_c),     Ab + (size_t)aw_m * CC + k0 + aw_c * 8);
            cp_async16(a_addr(da, aw_m, aw_c + 1), Ab + (size_t)aw_m * CC + k0 + aw_c * 8 + 8);
            cp_async16(b_addr(db, bw_k, bw_nc),     Bb + (size_t)(k0 + bw_k) * TT + bw_nc * 8);
            cp_async16(b_addr(db, bw_k, bw_nc + 1), Bb + (size_t)(k0 + bw_k) * TT + bw_nc * 8 + 8);
            CP_COMMIT();
        }
        CP_WAIT1();
        __syncthreads();

        const int NIT = CC / BK;   // 32
        for (int it = 0; it < NIT; ++it) {
            const int j = it + 2;
            if (j < NIT) {
                const int st = j % 3;
                const int k0 = j * BK;
                const uint32_t da = sA + st * A_STAGE;
                const uint32_t db = sB + st * B_STAGE;
                cp_async16(a_addr(da, aw_m, aw_c),     Ab + (size_t)aw_m * CC + k0 + aw_c * 8);
                cp_async16(a_addr(da, aw_m, aw_c + 1), Ab + (size_t)aw_m * CC + k0 + aw_c * 8 + 8);
                cp_async16(b_addr(db, bw_k, bw_nc),     Bb + (size_t)(k0 + bw_k) * TT + bw_nc * 8);
                cp_async16(b_addr(db, bw_k, bw_nc + 1), Bb + (size_t)(k0 + bw_k) * TT + bw_nc * 8 + 8);
            }
            CP_COMMIT();

            const int cs = it % 3;
            compute_k32(acc, sA + cs * A_STAGE, sB + cs * B_STAGE, 0,
                        warp_m, warp_n, lm_m, lm_c);

            CP_WAIT1();
            __syncthreads();
        }

        // epilogue: bias + mish -> hS (swizzled, rows = Cb, cols = t)
#pragma unroll
        for (int i = 0; i < 4; i++) {
            const int r0 = hh * 128 + warp_m * 64 + i * 16 + grp;
            const float bv0 = b_down[r0], bv1 = b_down[r0 + 8];
#pragma unroll
            for (int j = 0; j < 4; j++) {
                const int c = warp_n * 32 + j * 8 + 2 * lin;
                const int nc = c >> 3, off = (c & 7) * 2;
                __half2 v0 = __floats2half2_rn(mishf(acc[i][j][0] + bv0),
                                               mishf(acc[i][j][1] + bv0));
                __half2 v1 = __floats2half2_rn(mishf(acc[i][j][2] + bv1),
                                               mishf(acc[i][j][3] + bv1));
                uint32_t ad0 = b_addr(hS, r0, nc) + off;
                uint32_t ad1 = b_addr(hS, r0 + 8, nc) + off;
                asm volatile("st.shared.b32 [%0], %1;" :: "r"(ad0), "r"(*(uint32_t*)&v0));
                asm volatile("st.shared.b32 [%0], %1;" :: "r"(ad1), "r"(*(uint32_t*)&v1));
            }
        }
    }

    // ======================= PHASE 2: out = w_up @ hS ====================
    // prologue: vit 0,1  (A only; B lives in hS)
#pragma unroll
    for (int sst = 0; sst < 2; ++sst) {
        const int k0 = sst * BK;            // mt = 0
        const uint32_t da = sA + sst * A_STAGE;
        cp_async16(a_addr(da, aw_m, aw_c),     g_wu16 + (size_t)aw_m * CBOT + k0 + aw_c * 8);
        cp_async16(a_addr(da, aw_m, aw_c + 1), g_wu16 + (size_t)aw_m * CBOT + k0 + aw_c * 8 + 8);
        CP_COMMIT();
    }
    CP_WAIT1();
    __syncthreads();   // covers hS writes + stage 0

#pragma unroll
    for (int i = 0; i < 4; i++)
#pragma unroll
        for (int j = 0; j < 4; j++)
#pragma unroll
            for (int r = 0; r < 4; r++) acc[i][j][r] = 0.f;

    const int NV = 64;                       // 8 m-tiles x 8 k-iters
    for (int vit = 0; vit < NV; ++vit) {
        const int j = vit + 2;
        if (j < NV) {
            const int st = j % 3;
            const int mt2 = j >> 3;
            const int k0 = (j & 7) * BK;
            const uint32_t da = sA + st * A_STAGE;
            const __half* Ab2 = g_wu16 + (size_t)mt2 * 128 * CBOT;
            cp_async16(a_addr(da, aw_m, aw_c),     Ab2 + (size_t)aw_m * CBOT + k0 + aw_c * 8);
            cp_async16(a_addr(da, aw_m, aw_c + 1), Ab2 + (size_t)aw_m * CBOT + k0 + aw_c * 8 + 8);
        }
        CP_COMMIT();

        const int cs = vit % 3;
        compute_k32(acc, sA + cs * A_STAGE, hS, (vit & 7) * BK,
                    warp_m, warp_n, lm_m, lm_c);

        if ((vit & 7) == 7) {
            // epilogue for m-tile mt: bias + residual -> fp32 out
            const int mt = vit >> 3;
#pragma unroll
            for (int i = 0; i < 4; i++) {
                const int row = mt * 128 + warp_m * 64 + i * 16 + grp;
                const float bv0 = b_up[row], bv1 = b_up[row + 8];
                const size_t base0 = ((size_t)b * CC + row) * TT + t0;
#pragma unroll
                for (int j2 = 0; j2 < 4; j2++) {
                    const int c = warp_n * 32 + j2 * 8 + 2 * lin;
                    const size_t o0 = base0 + c;
                    const size_t o1 = o0 + (size_t)8 * TT;
                    float2 ra = *(const float2*)(xres + o0);
                    float2 rb = *(const float2*)(xres + o1);
                    *(float2*)(outp + o0) = make_float2(acc[i][j2][0] + bv0 + ra.x,
                                                        acc[i][j2][1] + bv0 + ra.y);
                    *(float2*)(outp + o1) = make_float2(acc[i][j2][2] + bv1 + rb.x,
                                                        acc[i][j2][3] + bv1 + rb.y);
                }
            }
#pragma unroll
            for (int i = 0; i < 4; i++)
#pragma unroll
                for (int j2 = 0; j2 < 4; j2++)
#pragma unroll
                    for (int r = 0; r < 4; r++) acc[i][j2][r] = 0.f;
        }

        CP_WAIT1();
        __syncthreads();
    }
}

// ---------------------------------------------------------------- launch ----
extern "C" void kernel_launch(void* const* d_in, const int* in_sizes, int n_in,
                              void* d_out, int out_size) {
    const float* x      = (const float*)d_in[0];
    const float* gamma  = (const float*)d_in[1];
    const float* beta   = (const float*)d_in[2];
    const float* w_down = (const float*)d_in[3];
    const float* b_down = (const float*)d_in[4];
    const float* w_up   = (const float*)d_in[5];
    const float* b_up   = (const float*)d_in[6];
    float* out = (float*)d_out;

    cudaFuncSetAttribute(gn_norm_kernel,
                         cudaFuncAttributeMaxDynamicSharedMemorySize, SMEM_GN);
    cudaFuncSetAttribute(mega_kernel,
                         cudaFuncAttributeMaxDynamicSharedMemorySize, SMEM_MEGA);

    gn_norm_kernel<<<BB * GG, 512, SMEM_GN>>>(x, gamma, beta);
    wconv_kernel<<<(CBOT * CC) / 256, 256>>>(w_down, w_up);
    mega_kernel<<<dim3(TT / TB, BB), 256, SMEM_MEGA>>>(x, b_down, b_up, out);
}